// round 6
// baseline (speedup 1.0000x reference)
#include <cuda_runtime.h>
#include <cstdint>
#include <cstddef>

#define TSIZE (1u << 18)
#define TMASK (TSIZE - 1u)
#define NLEV 16
#define P1 2654435761u
#define P2 805459861u

#define NBUCK (1u << 18)   // 64^3 buckets
#define NMAX (1 << 21)

// Device-global scratch (no allocation).
__device__ __align__(16) float2 g_hash[15u * TSIZE];
__device__ __align__(16) float2 g_dense[16 * 16 * 16];
__device__ unsigned g_count[NBUCK];
__device__ unsigned g_cursor[NBUCK];
__device__ float4   g_buf[NMAX];           // bucketed points {x,y,z,idx}

__device__ __forceinline__ int bucket_of(float cx, float cy, float cz) {
    int bx = min(63, max(0, (int)((cx + 1.0f) * 32.0f)));
    int by = min(63, max(0, (int)((cy + 1.0f) * 32.0f)));
    int bz = min(63, max(0, (int)((cz + 1.0f) * 32.0f)));
    return (bx * 64 + by) * 64 + bz;
}

// ---------------------------------------------------------------------------
// Repack tables to float2 + zero histogram.
// ---------------------------------------------------------------------------
__global__ void prep_kernel(const float* __restrict__ dense,
                            const float* __restrict__ hash) {
    unsigned i = blockIdx.x * blockDim.x + threadIdx.x;
    if (i < 15u * TSIZE) {
        unsigned l = i >> 18;
        unsigned t = i & TMASK;
        const float* base = hash + (size_t)l * (2u * TSIZE);
        g_hash[i] = make_float2(base[t], base[TSIZE + t]);
    }
    if (i < 4096u)
        g_dense[i] = make_float2(dense[i], dense[4096u + i]);
    if (i < NBUCK)
        g_count[i] = 0u;
}

__global__ void hist_kernel(const float* __restrict__ coords, int N) {
    int i = blockIdx.x * blockDim.x + threadIdx.x;
    if (i >= N) return;
    int b = bucket_of(coords[3 * i], coords[3 * i + 1], coords[3 * i + 2]);
    atomicAdd(&g_count[b], 1u);
}

// Single-block exclusive scan over 262144 counters -> g_cursor (two passes).
__global__ __launch_bounds__(1024)
void scan_kernel() {
    __shared__ unsigned part[1024];
    const int t = threadIdx.x;
    const unsigned base = (unsigned)t * 256u;
    unsigned s = 0;
    for (int j = 0; j < 256; ++j) s += g_count[base + j];
    part[t] = s;
    __syncthreads();
    for (int off = 1; off < 1024; off <<= 1) {
        unsigned v = 0;
        if (t >= off) v = part[t - off];
        __syncthreads();
        if (t >= off) part[t] += v;
        __syncthreads();
    }
    unsigned pre = (t == 0) ? 0u : part[t - 1];
    for (int j = 0; j < 256; ++j) {
        g_cursor[base + j] = pre;
        pre += g_count[base + j];
    }
}

__global__ void scatter_kernel(const float* __restrict__ coords, int N) {
    int i = blockIdx.x * blockDim.x + threadIdx.x;
    if (i >= N) return;
    float x = coords[3 * i], y = coords[3 * i + 1], z = coords[3 * i + 2];
    int b = bucket_of(x, y, z);
    unsigned slot = atomicAdd(&g_cursor[b], 1u);
    g_buf[slot] = make_float4(x, y, z, __int_as_float(i));
}

// ---------------------------------------------------------------------------
// Encode: Round-3 proven body, finer bucket order.
// ---------------------------------------------------------------------------
__global__ __launch_bounds__(256)
void encode_kernel(float* __restrict__ out, int N) {
    int i = blockIdx.x * blockDim.x + threadIdx.x;
    if (i >= N) return;

    const float4 pt = g_buf[i];
    const float cx = pt.x, cy = pt.y, cz = pt.z;
    const int idx = __float_as_int(pt.w);

    float4* __restrict__ out4 = reinterpret_cast<float4*>(out + (size_t)idx * 32);

    constexpr int RES[NLEV] = {16, 20, 25, 32, 40, 50, 64, 80,
                               101, 128, 161, 203, 256, 322, 406, 512};

    float4 obuf = make_float4(0.f, 0.f, 0.f, 0.f);

#pragma unroll
    for (int l = 0; l < NLEV; ++l) {
        const int res = RES[l];
        const float rm1 = (float)(res - 1);

        float px = fminf(fmaxf((cx + 1.0f) * 0.5f * rm1, 0.0f), rm1);
        float py = fminf(fmaxf((cy + 1.0f) * 0.5f * rm1, 0.0f), rm1);
        float pz = fminf(fmaxf((cz + 1.0f) * 0.5f * rm1, 0.0f), rm1);

        int ix0 = (int)px;  float wx = px - (float)ix0;
        int iy0 = (int)py;  float wy = py - (float)iy0;
        int iz0 = (int)pz;  float wz = pz - (float)iz0;
        int ix1 = min(ix0 + 1, res - 1);
        int iy1 = min(iy0 + 1, res - 1);
        int iz1 = min(iz0 + 1, res - 1);

        const float wxv0 = 1.0f - wx, wxv1 = wx;
        const float wyv0 = 1.0f - wy, wyv1 = wy;
        const float wzv0 = 1.0f - wz, wzv1 = wz;

        float2 f[8];
        float  wg[8];

        if (l == 0) {
#pragma unroll
            for (int c = 0; c < 8; ++c) {
                const int xi = (c & 4) ? ix1 : ix0;
                const int yi = (c & 2) ? iy1 : iy0;
                const int zi = (c & 1) ? iz1 : iz0;
                f[c] = __ldg(&g_dense[(xi * 16 + yi) * 16 + zi]);
                wg[c] = ((c & 4) ? wxv1 : wxv0) *
                        ((c & 2) ? wyv1 : wyv0) *
                        ((c & 1) ? wzv1 : wzv0);
            }
        } else {
            const float2* __restrict__ tbl = g_hash + (size_t)(l - 1) * TSIZE;
            const unsigned hx0 = (unsigned)ix0;  // prime 1
            const unsigned hx1 = (unsigned)ix1;
            const unsigned hy0 = (unsigned)iy0 * P1;
            const unsigned hy1 = (unsigned)iy1 * P1;
            const unsigned hz0 = (unsigned)iz0 * P2;
            const unsigned hz1 = (unsigned)iz1 * P2;
#pragma unroll
            for (int c = 0; c < 8; ++c) {
                const unsigned h = (((c & 4) ? hx1 : hx0) ^
                                    ((c & 2) ? hy1 : hy0) ^
                                    ((c & 1) ? hz1 : hz0)) & TMASK;
                f[c] = __ldg(&tbl[h]);
                wg[c] = ((c & 4) ? wxv1 : wxv0) *
                        ((c & 2) ? wyv1 : wyv0) *
                        ((c & 1) ? wzv1 : wzv0);
            }
        }

        float a0 = 0.0f, a1 = 0.0f;
#pragma unroll
        for (int c = 0; c < 8; ++c) {
            a0 = fmaf(f[c].x, wg[c], a0);
            a1 = fmaf(f[c].y, wg[c], a1);
        }

        if ((l & 1) == 0) {
            obuf.x = a0; obuf.y = a1;
        } else {
            obuf.z = a0; obuf.w = a1;
            out4[l >> 1] = obuf;
        }
    }
}

// ---------------------------------------------------------------------------
// kernel_launch: prep -> hist -> scan -> scatter -> encode
// ---------------------------------------------------------------------------
extern "C" void kernel_launch(void* const* d_in, const int* in_sizes, int n_in,
                              void* d_out, int out_size) {
    const float* coords = (const float*)d_in[0];
    const float* dense  = (const float*)d_in[1];
    const float* hash   = (const float*)d_in[2];
    float* out = (float*)d_out;

    const int N = in_sizes[0] / 3;
    const int nb = (N + 255) / 256;

    const unsigned prep_total = 15u * TSIZE;
    prep_kernel<<<(prep_total + 255u) / 256u, 256>>>(dense, hash);
    hist_kernel<<<nb, 256>>>(coords, N);
    scan_kernel<<<1, 1024>>>();
    scatter_kernel<<<nb, 256>>>(coords, N);
    encode_kernel<<<nb, 256>>>(out, N);
}

// round 7
// speedup vs baseline: 1.9605x; 1.9605x over previous
#include <cuda_runtime.h>
#include <cstdint>
#include <cstddef>

#define TSIZE (1u << 18)
#define TMASK (TSIZE - 1u)
#define NLEV 16
#define P1 2654435761u
#define P2 805459861u

#define NBUCK (1u << 18)   // 64^3 buckets
#define NMAX (1 << 21)

// Device-global scratch (no allocation).
__device__ __align__(16) float2 g_hash[15u * TSIZE];
__device__ __align__(16) float2 g_dense[16 * 16 * 16];
__device__ unsigned g_count[NBUCK];
__device__ unsigned g_cursor[NBUCK];
__device__ unsigned g_bsum[256];
__device__ unsigned g_boff[256];
__device__ float4   g_buf[NMAX];           // bucketed points {x,y,z,idx}

__device__ __forceinline__ int bucket_of(float cx, float cy, float cz) {
    int bx = min(63, max(0, (int)((cx + 1.0f) * 32.0f)));
    int by = min(63, max(0, (int)((cy + 1.0f) * 32.0f)));
    int bz = min(63, max(0, (int)((cz + 1.0f) * 32.0f)));
    return (bx * 64 + by) * 64 + bz;
}

// ---------------------------------------------------------------------------
// Fused prep: repack tables + zero counters + histogram points.
// Zeroing (i < NBUCK) finishes before hist atomics from other blocks? No —
// so zero in its own region ordering-free: counters are zeroed by threads
// i < NBUCK and incremented only in hist_kernel (separate launch). Keep hist
// separate for correctness of the zero/increment order.
// ---------------------------------------------------------------------------
__global__ void prep_kernel(const float* __restrict__ dense,
                            const float* __restrict__ hash) {
    unsigned i = blockIdx.x * blockDim.x + threadIdx.x;
    if (i < 15u * TSIZE) {
        unsigned l = i >> 18;
        unsigned t = i & TMASK;
        const float* base = hash + (size_t)l * (2u * TSIZE);
        g_hash[i] = make_float2(base[t], base[TSIZE + t]);
    }
    if (i < 4096u)
        g_dense[i] = make_float2(dense[i], dense[4096u + i]);
    if (i < NBUCK)
        g_count[i] = 0u;
}

__global__ void hist_kernel(const float* __restrict__ coords, int N) {
    int i = blockIdx.x * blockDim.x + threadIdx.x;
    if (i >= N) return;
    int b = bucket_of(coords[3 * i], coords[3 * i + 1], coords[3 * i + 2]);
    atomicAdd(&g_count[b], 1u);
}

// ---------------------------------------------------------------------------
// Parallel scan over 262144 counters: per-block scan -> top scan -> apply.
// ---------------------------------------------------------------------------
__global__ __launch_bounds__(1024)
void scan_part_kernel() {
    __shared__ unsigned sh[1024];
    const int b = blockIdx.x, t = threadIdx.x;
    const unsigned v = g_count[b * 1024 + t];
    sh[t] = v;
    __syncthreads();
    for (int off = 1; off < 1024; off <<= 1) {
        unsigned u = 0;
        if (t >= off) u = sh[t - off];
        __syncthreads();
        sh[t] += u;
        __syncthreads();
    }
    g_cursor[b * 1024 + t] = sh[t] - v;   // exclusive within block
    if (t == 1023) g_bsum[b] = sh[t];
}

__global__ __launch_bounds__(256)
void scan_top_kernel() {
    __shared__ unsigned sh[256];
    const int t = threadIdx.x;
    const unsigned v = g_bsum[t];
    sh[t] = v;
    __syncthreads();
    for (int off = 1; off < 256; off <<= 1) {
        unsigned u = 0;
        if (t >= off) u = sh[t - off];
        __syncthreads();
        sh[t] += u;
        __syncthreads();
    }
    g_boff[t] = sh[t] - v;                // exclusive block offsets
}

__global__ __launch_bounds__(1024)
void scan_apply_kernel() {
    const unsigned i = blockIdx.x * 1024u + threadIdx.x;
    g_cursor[i] += g_boff[blockIdx.x];
}

__global__ void scatter_kernel(const float* __restrict__ coords, int N) {
    int i = blockIdx.x * blockDim.x + threadIdx.x;
    if (i >= N) return;
    float x = coords[3 * i], y = coords[3 * i + 1], z = coords[3 * i + 2];
    int b = bucket_of(x, y, z);
    unsigned slot = atomicAdd(&g_cursor[b], 1u);
    g_buf[slot] = make_float4(x, y, z, __int_as_float(i));
}

// ---------------------------------------------------------------------------
// Encode: Round-3 proven body, 64^3 bucket order.
// ---------------------------------------------------------------------------
__global__ __launch_bounds__(256)
void encode_kernel(float* __restrict__ out, int N) {
    int i = blockIdx.x * blockDim.x + threadIdx.x;
    if (i >= N) return;

    const float4 pt = g_buf[i];
    const float cx = pt.x, cy = pt.y, cz = pt.z;
    const int idx = __float_as_int(pt.w);

    float4* __restrict__ out4 = reinterpret_cast<float4*>(out + (size_t)idx * 32);

    constexpr int RES[NLEV] = {16, 20, 25, 32, 40, 50, 64, 80,
                               101, 128, 161, 203, 256, 322, 406, 512};

    float4 obuf = make_float4(0.f, 0.f, 0.f, 0.f);

#pragma unroll
    for (int l = 0; l < NLEV; ++l) {
        const int res = RES[l];
        const float rm1 = (float)(res - 1);

        float px = fminf(fmaxf((cx + 1.0f) * 0.5f * rm1, 0.0f), rm1);
        float py = fminf(fmaxf((cy + 1.0f) * 0.5f * rm1, 0.0f), rm1);
        float pz = fminf(fmaxf((cz + 1.0f) * 0.5f * rm1, 0.0f), rm1);

        int ix0 = (int)px;  float wx = px - (float)ix0;
        int iy0 = (int)py;  float wy = py - (float)iy0;
        int iz0 = (int)pz;  float wz = pz - (float)iz0;
        int ix1 = min(ix0 + 1, res - 1);
        int iy1 = min(iy0 + 1, res - 1);
        int iz1 = min(iz0 + 1, res - 1);

        const float wxv0 = 1.0f - wx, wxv1 = wx;
        const float wyv0 = 1.0f - wy, wyv1 = wy;
        const float wzv0 = 1.0f - wz, wzv1 = wz;

        float2 f[8];
        float  wg[8];

        if (l == 0) {
#pragma unroll
            for (int c = 0; c < 8; ++c) {
                const int xi = (c & 4) ? ix1 : ix0;
                const int yi = (c & 2) ? iy1 : iy0;
                const int zi = (c & 1) ? iz1 : iz0;
                f[c] = __ldg(&g_dense[(xi * 16 + yi) * 16 + zi]);
                wg[c] = ((c & 4) ? wxv1 : wxv0) *
                        ((c & 2) ? wyv1 : wyv0) *
                        ((c & 1) ? wzv1 : wzv0);
            }
        } else {
            const float2* __restrict__ tbl = g_hash + (size_t)(l - 1) * TSIZE;
            const unsigned hx0 = (unsigned)ix0;  // prime 1
            const unsigned hx1 = (unsigned)ix1;
            const unsigned hy0 = (unsigned)iy0 * P1;
            const unsigned hy1 = (unsigned)iy1 * P1;
            const unsigned hz0 = (unsigned)iz0 * P2;
            const unsigned hz1 = (unsigned)iz1 * P2;
#pragma unroll
            for (int c = 0; c < 8; ++c) {
                const unsigned h = (((c & 4) ? hx1 : hx0) ^
                                    ((c & 2) ? hy1 : hy0) ^
                                    ((c & 1) ? hz1 : hz0)) & TMASK;
                f[c] = __ldg(&tbl[h]);
                wg[c] = ((c & 4) ? wxv1 : wxv0) *
                        ((c & 2) ? wyv1 : wyv0) *
                        ((c & 1) ? wzv1 : wzv0);
            }
        }

        float a0 = 0.0f, a1 = 0.0f;
#pragma unroll
        for (int c = 0; c < 8; ++c) {
            a0 = fmaf(f[c].x, wg[c], a0);
            a1 = fmaf(f[c].y, wg[c], a1);
        }

        if ((l & 1) == 0) {
            obuf.x = a0; obuf.y = a1;
        } else {
            obuf.z = a0; obuf.w = a1;
            out4[l >> 1] = obuf;
        }
    }
}

// ---------------------------------------------------------------------------
// kernel_launch: prep -> hist -> scan(3) -> scatter -> encode
// ---------------------------------------------------------------------------
extern "C" void kernel_launch(void* const* d_in, const int* in_sizes, int n_in,
                              void* d_out, int out_size) {
    const float* coords = (const float*)d_in[0];
    const float* dense  = (const float*)d_in[1];
    const float* hash   = (const float*)d_in[2];
    float* out = (float*)d_out;

    const int N = in_sizes[0] / 3;
    const int nb = (N + 255) / 256;

    const unsigned prep_total = 15u * TSIZE;
    prep_kernel<<<(prep_total + 255u) / 256u, 256>>>(dense, hash);
    hist_kernel<<<nb, 256>>>(coords, N);
    scan_part_kernel<<<NBUCK / 1024, 1024>>>();
    scan_top_kernel<<<1, 256>>>();
    scan_apply_kernel<<<NBUCK / 1024, 1024>>>();
    scatter_kernel<<<nb, 256>>>(coords, N);
    encode_kernel<<<nb, 256>>>(out, N);
}

// round 8
// speedup vs baseline: 1.9670x; 1.0033x over previous
#include <cuda_runtime.h>
#include <cstdint>
#include <cstddef>

#define TSIZE (1u << 18)
#define TMASK (TSIZE - 1u)
#define NLEV 16
#define P1 2654435761u
#define P2 805459861u

#define NBUCK (1u << 18)   // 64^3 buckets
#define NMAX (1 << 21)

// Device-global scratch (no allocation).
// g_count: zero at module load; scan_part re-zeroes it after consuming, so it
// is zero at the start of every kernel_launch invocation (incl. graph replays).
__device__ __align__(16) float2 g_hash[15u * TSIZE];
__device__ __align__(16) float2 g_dense[16 * 16 * 16];
__device__ unsigned g_count[NBUCK];
__device__ unsigned g_cursor[NBUCK];
__device__ unsigned g_bsum[256];
__device__ unsigned g_boff[256];
__device__ float4   g_buf[NMAX];           // bucketed points {x,y,z,idx}

__device__ __forceinline__ int bucket_of(float cx, float cy, float cz) {
    int bx = min(63, max(0, (int)((cx + 1.0f) * 32.0f)));
    int by = min(63, max(0, (int)((cy + 1.0f) * 32.0f)));
    int bz = min(63, max(0, (int)((cz + 1.0f) * 32.0f)));
    return (bx * 64 + by) * 64 + bz;
}

// ---------------------------------------------------------------------------
// Fused prep: repack tables + histogram points (g_count pre-zeroed, see above).
// Grid covers 15*2^18 = 3.93M threads >= N = 2.09M.
// ---------------------------------------------------------------------------
__global__ void prep_kernel(const float* __restrict__ dense,
                            const float* __restrict__ hash,
                            const float* __restrict__ coords, int N) {
    unsigned i = blockIdx.x * blockDim.x + threadIdx.x;
    if (i < 15u * TSIZE) {
        unsigned l = i >> 18;
        unsigned t = i & TMASK;
        const float* base = hash + (size_t)l * (2u * TSIZE);
        g_hash[i] = make_float2(base[t], base[TSIZE + t]);
    }
    if (i < 4096u)
        g_dense[i] = make_float2(dense[i], dense[4096u + i]);
    if (i < (unsigned)N) {
        int b = bucket_of(coords[3 * i], coords[3 * i + 1], coords[3 * i + 2]);
        atomicAdd(&g_count[b], 1u);
    }
}

// ---------------------------------------------------------------------------
// Parallel scan over 262144 counters: per-block scan -> top scan -> apply.
// scan_part also re-zeroes g_count for the next run.
// ---------------------------------------------------------------------------
__global__ __launch_bounds__(1024)
void scan_part_kernel() {
    __shared__ unsigned sh[1024];
    const int b = blockIdx.x, t = threadIdx.x;
    const unsigned gi = b * 1024 + t;
    const unsigned v = g_count[gi];
    g_count[gi] = 0u;                      // self-clean for next invocation
    sh[t] = v;
    __syncthreads();
    for (int off = 1; off < 1024; off <<= 1) {
        unsigned u = 0;
        if (t >= off) u = sh[t - off];
        __syncthreads();
        sh[t] += u;
        __syncthreads();
    }
    g_cursor[gi] = sh[t] - v;              // exclusive within block
    if (t == 1023) g_bsum[b] = sh[t];
}

__global__ __launch_bounds__(256)
void scan_top_kernel() {
    __shared__ unsigned sh[256];
    const int t = threadIdx.x;
    const unsigned v = g_bsum[t];
    sh[t] = v;
    __syncthreads();
    for (int off = 1; off < 256; off <<= 1) {
        unsigned u = 0;
        if (t >= off) u = sh[t - off];
        __syncthreads();
        sh[t] += u;
        __syncthreads();
    }
    g_boff[t] = sh[t] - v;                 // exclusive block offsets
}

__global__ __launch_bounds__(1024)
void scan_apply_kernel() {
    const unsigned i = blockIdx.x * 1024u + threadIdx.x;
    g_cursor[i] += g_boff[blockIdx.x];
}

__global__ void scatter_kernel(const float* __restrict__ coords, int N) {
    int i = blockIdx.x * blockDim.x + threadIdx.x;
    if (i >= N) return;
    float x = coords[3 * i], y = coords[3 * i + 1], z = coords[3 * i + 2];
    int b = bucket_of(x, y, z);
    unsigned slot = atomicAdd(&g_cursor[b], 1u);
    g_buf[slot] = make_float4(x, y, z, __int_as_float(i));
}

// ---------------------------------------------------------------------------
// Encode: proven body, 64^3 bucket order.
// ---------------------------------------------------------------------------
__global__ __launch_bounds__(256)
void encode_kernel(float* __restrict__ out, int N) {
    int i = blockIdx.x * blockDim.x + threadIdx.x;
    if (i >= N) return;

    const float4 pt = g_buf[i];
    const float cx = pt.x, cy = pt.y, cz = pt.z;
    const int idx = __float_as_int(pt.w);

    float4* __restrict__ out4 = reinterpret_cast<float4*>(out + (size_t)idx * 32);

    constexpr int RES[NLEV] = {16, 20, 25, 32, 40, 50, 64, 80,
                               101, 128, 161, 203, 256, 322, 406, 512};

    float4 obuf = make_float4(0.f, 0.f, 0.f, 0.f);

#pragma unroll
    for (int l = 0; l < NLEV; ++l) {
        const int res = RES[l];
        const float rm1 = (float)(res - 1);

        float px = fminf(fmaxf((cx + 1.0f) * 0.5f * rm1, 0.0f), rm1);
        float py = fminf(fmaxf((cy + 1.0f) * 0.5f * rm1, 0.0f), rm1);
        float pz = fminf(fmaxf((cz + 1.0f) * 0.5f * rm1, 0.0f), rm1);

        int ix0 = (int)px;  float wx = px - (float)ix0;
        int iy0 = (int)py;  float wy = py - (float)iy0;
        int iz0 = (int)pz;  float wz = pz - (float)iz0;
        int ix1 = min(ix0 + 1, res - 1);
        int iy1 = min(iy0 + 1, res - 1);
        int iz1 = min(iz0 + 1, res - 1);

        const float wxv0 = 1.0f - wx, wxv1 = wx;
        const float wyv0 = 1.0f - wy, wyv1 = wy;
        const float wzv0 = 1.0f - wz, wzv1 = wz;

        float2 f[8];
        float  wg[8];

        if (l == 0) {
#pragma unroll
            for (int c = 0; c < 8; ++c) {
                const int xi = (c & 4) ? ix1 : ix0;
                const int yi = (c & 2) ? iy1 : iy0;
                const int zi = (c & 1) ? iz1 : iz0;
                f[c] = __ldg(&g_dense[(xi * 16 + yi) * 16 + zi]);
                wg[c] = ((c & 4) ? wxv1 : wxv0) *
                        ((c & 2) ? wyv1 : wyv0) *
                        ((c & 1) ? wzv1 : wzv0);
            }
        } else {
            const float2* __restrict__ tbl = g_hash + (size_t)(l - 1) * TSIZE;
            const unsigned hx0 = (unsigned)ix0;  // prime 1
            const unsigned hx1 = (unsigned)ix1;
            const unsigned hy0 = (unsigned)iy0 * P1;
            const unsigned hy1 = (unsigned)iy1 * P1;
            const unsigned hz0 = (unsigned)iz0 * P2;
            const unsigned hz1 = (unsigned)iz1 * P2;
#pragma unroll
            for (int c = 0; c < 8; ++c) {
                const unsigned h = (((c & 4) ? hx1 : hx0) ^
                                    ((c & 2) ? hy1 : hy0) ^
                                    ((c & 1) ? hz1 : hz0)) & TMASK;
                f[c] = __ldg(&tbl[h]);
                wg[c] = ((c & 4) ? wxv1 : wxv0) *
                        ((c & 2) ? wyv1 : wyv0) *
                        ((c & 1) ? wzv1 : wzv0);
            }
        }

        float a0 = 0.0f, a1 = 0.0f;
#pragma unroll
        for (int c = 0; c < 8; ++c) {
            a0 = fmaf(f[c].x, wg[c], a0);
            a1 = fmaf(f[c].y, wg[c], a1);
        }

        if ((l & 1) == 0) {
            obuf.x = a0; obuf.y = a1;
        } else {
            obuf.z = a0; obuf.w = a1;
            out4[l >> 1] = obuf;
        }
    }
}

// ---------------------------------------------------------------------------
// kernel_launch: prep(repack+hist) -> scan(3) -> scatter -> encode  (6 launches)
// ---------------------------------------------------------------------------
extern "C" void kernel_launch(void* const* d_in, const int* in_sizes, int n_in,
                              void* d_out, int out_size) {
    const float* coords = (const float*)d_in[0];
    const float* dense  = (const float*)d_in[1];
    const float* hash   = (const float*)d_in[2];
    float* out = (float*)d_out;

    const int N = in_sizes[0] / 3;
    const int nb = (N + 255) / 256;

    const unsigned prep_total = 15u * TSIZE;
    prep_kernel<<<(prep_total + 255u) / 256u, 256>>>(dense, hash, coords, N);
    scan_part_kernel<<<NBUCK / 1024, 1024>>>();
    scan_top_kernel<<<1, 256>>>();
    scan_apply_kernel<<<NBUCK / 1024, 1024>>>();
    scatter_kernel<<<nb, 256>>>(coords, N);
    encode_kernel<<<nb, 256>>>(out, N);
}